// round 15
// baseline (speedup 1.0000x reference)
#include <cuda_runtime.h>
#include <cuda_fp16.h>
#include <cstdint>

// Problem constants (fixed shapes from reference)
#define N_NODES 32768      // B*S = 64*512
#define IN_F    256
#define OUT_F   256
#define NBASES  3
#define N_EDGES 262144
#define KDIM    768        // NBASES * IN_F: GEMM K dimension
#define BUCKET_CAP 64      // per-dst bucket (deg ~ Poisson(8); P(>64) ~ 1e-40)

// Scratch
__device__ __half g_h[(size_t)N_NODES * IN_F];            // fp16 text (16MB, L2-resident)
__device__ __half g_z[(size_t)N_NODES * KDIM];            // aggregated z[d][b][i] fp16, 48MB
__device__ __half g_Bh[(size_t)KDIM * OUT_F];             // fp16 bases stacked [(b,i)][o]
// Bucketed edges; spack = src | (rel<<17). INVARIANT: g_cnt == 0 at every
// kernel_launch entry (zero-initialized at load; edge_agg re-zeroes it each
// call after consuming). This lets scatter run concurrently with the splits.
__device__ int g_cnt[N_NODES];
__device__ int g_spack[N_NODES * BUCKET_CAP];

__device__ __forceinline__ uint32_t smem_u32(const void* p) {
    uint32_t a;
    asm("{ .reg .u64 t; cvta.to.shared.u64 t, %1; cvt.u32.u64 %0, t; }" : "=r"(a) : "l"(p));
    return a;
}

// ---------------------------------------------------------------------------
// Prep kernel: fp16 converts (text+bases) AND bucket scatter, one launch.
// Block ranges are disjoint; scatter needs only the cross-call g_cnt invariant.
// ---------------------------------------------------------------------------
#define N_TEXT4 (N_NODES * IN_F / 4)
#define N_BASE4 (KDIM * OUT_F / 4)
#define SPLIT_BLOCKS ((N_TEXT4 + N_BASE4) / 256)   // 8384
#define SCATTER_BLOCKS (N_EDGES / 256)             // 1024
#define PREP_BLOCKS (SPLIT_BLOCKS + SCATTER_BLOCKS)

__global__ void prep_kernel(const float* __restrict__ text, const float* __restrict__ bases,
                            const int* __restrict__ src, const int* __restrict__ dst,
                            const int* __restrict__ rel)
{
    const int bi = blockIdx.x;
    if (bi < SPLIT_BLOCKS) {
        int i = bi * 256 + threadIdx.x;
        const float* s;
        __half2* d;
        int j;
        if (i < N_TEXT4) {
            s = text; j = i;
            d = (__half2*)g_h;
        } else {
            s = bases; j = i - N_TEXT4;
            d = (__half2*)g_Bh;
        }
        float4 v = ((const float4*)s)[j];
        d[2 * j + 0] = __halves2half2(__float2half_rn(v.x), __float2half_rn(v.y));
        d[2 * j + 1] = __halves2half2(__float2half_rn(v.z), __float2half_rn(v.w));
    } else {
        int e = (bi - SPLIT_BLOCKS) * 256 + threadIdx.x;
        int d = dst[e];
        int pos = atomicAdd(&g_cnt[d], 1);
        if (pos < BUCKET_CAP)
            g_spack[d * BUCKET_CAP + pos] = src[e] | (rel[e] << 17);
    }
}

// ---------------------------------------------------------------------------
// Edge aggregation in INPUT space: z[d,b,:] = sum_{e: dst=d} comp[rel_e,b]*h[src_e,:]
// One warp per dst node, reading its bucket. 8-edge batches, loads grouped
// before FMAs (MLP=8). FMAs use packed fma.rn.f32x2 (2 FMAs/instr, identical
// rounding). Zeroes g_cnt[d] after consuming (restores cross-call invariant).
// ---------------------------------------------------------------------------
__device__ __forceinline__ uint64_t pk2(float a, float b) {
    uint64_t r;
    asm("mov.b64 %0, {%1, %2};" : "=l"(r) : "f"(a), "f"(b));
    return r;
}
__device__ __forceinline__ void fma2(uint64_t& c, uint64_t a, uint64_t b) {
    asm("fma.rn.f32x2 %0, %1, %2, %0;" : "+l"(c) : "l"(a), "l"(b));
}
__device__ __forceinline__ float2 upk2(uint64_t v) {
    float2 r;
    asm("mov.b64 {%0, %1}, %2;" : "=f"(r.x), "=f"(r.y) : "l"(v));
    return r;
}

__device__ __forceinline__ void agg_q(uint64_t* A0, uint64_t* A1, uint64_t* A2,
                                      uint4 q, const float* sc, int r3)
{
    const uint64_t C0 = pk2(sc[r3], sc[r3]);
    const uint64_t C1 = pk2(sc[r3 + 1], sc[r3 + 1]);
    const uint64_t C2 = pk2(sc[r3 + 2], sc[r3 + 2]);
    uint32_t qs[4] = {q.x, q.y, q.z, q.w};
    #pragma unroll
    for (int k = 0; k < 4; k++) {
        float2 v = __half22float2(*(__half2*)&qs[k]);
        uint64_t pv = pk2(v.x, v.y);
        fma2(A0[k], C0, pv);
        fma2(A1[k], C1, pv);
        fma2(A2[k], C2, pv);
    }
}

__global__ void __launch_bounds__(256, 3) edge_agg_kernel(const float* __restrict__ comp)
{
    __shared__ float scomp[NBASES * 40];
    if (threadIdx.x < NBASES * 40) scomp[threadIdx.x] = comp[threadIdx.x];
    __syncthreads();

    const int d    = blockIdx.x * 8 + (threadIdx.x >> 5);
    const int lane = threadIdx.x & 31;

    uint64_t A0[4] = {}, A1[4] = {}, A2[4] = {};

    const int beg = d * BUCKET_CAP;
    int num = g_cnt[d];
    if (lane == 0) g_cnt[d] = 0;          // restore invariant for next call
    if (num > BUCKET_CAP) num = BUCKET_CAP;
    const uint4* hp = (const uint4*)g_h;  // 32 uint4 per node row

    int i = 0;
    for (; i + 8 <= num; i += 8) {
        int p[8];
        #pragma unroll
        for (int j = 0; j < 8; j++) p[j] = g_spack[beg + i + j];
        uint4 q[8];
        #pragma unroll
        for (int j = 0; j < 8; j++) q[j] = __ldg(hp + (size_t)(p[j] & 0x1FFFF) * 32 + lane);
        #pragma unroll
        for (int j = 0; j < 8; j++) agg_q(A0, A1, A2, q[j], scomp, (p[j] >> 17) * 3);
    }
    if (i + 4 <= num) {
        int p[4];
        #pragma unroll
        for (int j = 0; j < 4; j++) p[j] = g_spack[beg + i + j];
        uint4 q[4];
        #pragma unroll
        for (int j = 0; j < 4; j++) q[j] = __ldg(hp + (size_t)(p[j] & 0x1FFFF) * 32 + lane);
        #pragma unroll
        for (int j = 0; j < 4; j++) agg_q(A0, A1, A2, q[j], scomp, (p[j] >> 17) * 3);
        i += 4;
    }
    for (; i < num; i++) {
        int p = g_spack[beg + i];
        uint4 q = __ldg(hp + (size_t)(p & 0x1FFFF) * 32 + lane);
        agg_q(A0, A1, A2, q, scomp, (p >> 17) * 3);
    }

    // Store z[d][b][8*lane..8*lane+7] as fp16
    __half* zp = g_z + (size_t)d * KDIM + 8 * lane;
    uint4 o;
    float2 r0, r1;
    r0 = upk2(A0[0]); r1 = upk2(A0[1]);
    *(__half2*)&o.x = __floats2half2_rn(r0.x, r0.y); *(__half2*)&o.y = __floats2half2_rn(r1.x, r1.y);
    r0 = upk2(A0[2]); r1 = upk2(A0[3]);
    *(__half2*)&o.z = __floats2half2_rn(r0.x, r0.y); *(__half2*)&o.w = __floats2half2_rn(r1.x, r1.y);
    *(uint4*)zp = o;
    r0 = upk2(A1[0]); r1 = upk2(A1[1]);
    *(__half2*)&o.x = __floats2half2_rn(r0.x, r0.y); *(__half2*)&o.y = __floats2half2_rn(r1.x, r1.y);
    r0 = upk2(A1[2]); r1 = upk2(A1[3]);
    *(__half2*)&o.z = __floats2half2_rn(r0.x, r0.y); *(__half2*)&o.w = __floats2half2_rn(r1.x, r1.y);
    *(uint4*)(zp + 256) = o;
    r0 = upk2(A2[0]); r1 = upk2(A2[1]);
    *(__half2*)&o.x = __floats2half2_rn(r0.x, r0.y); *(__half2*)&o.y = __floats2half2_rn(r1.x, r1.y);
    r0 = upk2(A2[2]); r1 = upk2(A2[3]);
    *(__half2*)&o.z = __floats2half2_rn(r0.x, r0.y); *(__half2*)&o.w = __floats2half2_rn(r1.x, r1.y);
    *(uint4*)(zp + 512) = o;
}

// ---------------------------------------------------------------------------
// Tensor-core GEMM: out = relu(bias + z @ B), K=768. At HMMA floor (47.8us).
// CTA 128x128, warp tile 32x64 (4M x 2N warps), K chunked by 64,
// 2-stage cp.async, 2 CTAs/SM.
// ---------------------------------------------------------------------------
#define SAROW 144u                 // 64 halfs + 16B pad
#define SBROW 272u                 // 128 halfs + 16B pad
#define OFF_B  18432u              // 128*144
#define STAGE_B 35840u             // A 18432 | B 17408
#define GEMM_SMEM (2 * 35840)

__device__ __forceinline__ void ldm_x4(uint32_t* r, uint32_t addr) {
    asm volatile("ldmatrix.sync.aligned.m8n8.x4.shared.b16 {%0,%1,%2,%3}, [%4];"
                 : "=r"(r[0]), "=r"(r[1]), "=r"(r[2]), "=r"(r[3]) : "r"(addr));
}
__device__ __forceinline__ void ldm_x4t(uint32_t* r, uint32_t addr) {
    asm volatile("ldmatrix.sync.aligned.m8n8.x4.trans.shared.b16 {%0,%1,%2,%3}, [%4];"
                 : "=r"(r[0]), "=r"(r[1]), "=r"(r[2]), "=r"(r[3]) : "r"(addr));
}
__device__ __forceinline__ void mma16816(float* c, const uint32_t* a, const uint32_t* b) {
    asm volatile("mma.sync.aligned.m16n8k16.row.col.f32.f16.f16.f32 "
                 "{%0,%1,%2,%3}, {%4,%5,%6,%7}, {%8,%9}, {%0,%1,%2,%3};"
                 : "+f"(c[0]), "+f"(c[1]), "+f"(c[2]), "+f"(c[3])
                 : "r"(a[0]), "r"(a[1]), "r"(a[2]), "r"(a[3]), "r"(b[0]), "r"(b[1]));
}
__device__ __forceinline__ void cpa16(uint32_t dst, const void* src) {
    asm volatile("cp.async.cg.shared.global [%0], [%1], 16;" :: "r"(dst), "l"(src) : "memory");
}

__device__ __forceinline__ void gemm_load_chunk(uint32_t sb, int s, int m0, int n0, int c, int tid)
{
    const uint32_t so = sb + (uint32_t)s * STAGE_B;
    const int k0 = c << 6;
    // A (= z): 128 rows x 64 halfs (8 x 16B per row) -> 1024 chunks, 4/thread
    #pragma unroll
    for (int i = 0; i < 4; i++) {
        int idx = tid + (i << 8);
        int row = idx >> 3, ch = idx & 7;
        size_t goff = (size_t)(m0 + row) * KDIM + k0 + (ch << 3);
        cpa16(so + (uint32_t)row * SAROW + (uint32_t)(ch << 4), g_z + goff);
    }
    // B: 64 k-rows x 128 halfs (16 x 16B per row) -> 1024 chunks, 4/thread
    #pragma unroll
    for (int i = 0; i < 4; i++) {
        int idx = tid + (i << 8);
        int row = idx >> 4, ch = idx & 15;
        size_t goff = (size_t)(k0 + row) * OUT_F + n0 + (ch << 3);
        cpa16(so + OFF_B + (uint32_t)row * SBROW + (uint32_t)(ch << 4), g_Bh + goff);
    }
    asm volatile("cp.async.commit_group;" ::: "memory");
}

__global__ void __launch_bounds__(256, 2) gemm_tc_kernel(
    const float* __restrict__ bias, float* __restrict__ out)
{
    extern __shared__ char smem[];
    const uint32_t sb = smem_u32(smem);
    const int tid  = threadIdx.x;
    const int wid  = tid >> 5;
    const int lane = tid & 31;
    const int wm = wid >> 1;          // 0..3 (M)
    const int wn = wid & 1;           // 0..1 (N)
    const int n0 = blockIdx.x << 7;
    const int m0 = blockIdx.y << 7;

    const uint32_t a_lane = (uint32_t)((lane & 15) * SAROW + (lane >> 4) * 16) + (uint32_t)(wm * 32) * SAROW;
    const uint32_t b_lane = (uint32_t)((lane & 15) * SBROW + (lane >> 4) * 16) + (uint32_t)(wn * 128);

    float acc[2][8][4];
    #pragma unroll
    for (int mt = 0; mt < 2; mt++)
        #pragma unroll
        for (int nt = 0; nt < 8; nt++)
            #pragma unroll
            for (int q = 0; q < 4; q++) acc[mt][nt][q] = 0.0f;

    gemm_load_chunk(sb, 0, m0, n0, 0, tid);

    for (int c = 0; c < 12; c++) {
        if (c + 1 < 12) {
            gemm_load_chunk(sb, (c + 1) & 1, m0, n0, c + 1, tid);
            asm volatile("cp.async.wait_group 1;" ::: "memory");
        } else {
            asm volatile("cp.async.wait_group 0;" ::: "memory");
        }
        __syncthreads();

        const uint32_t so = sb + (uint32_t)(c & 1) * STAGE_B;
        #pragma unroll
        for (int kk = 0; kk < 4; kk++) {
            uint32_t ah[2][4];
            #pragma unroll
            for (int mt = 0; mt < 2; mt++)
                ldm_x4(ah[mt], so + a_lane + (uint32_t)(mt * 16) * SAROW + (uint32_t)(kk * 32));
            #pragma unroll
            for (int p = 0; p < 4; p++) {
                uint32_t bh[4];
                ldm_x4t(bh, so + OFF_B + b_lane + (uint32_t)(kk * 16) * SBROW + (uint32_t)(p * 32));
                #pragma unroll
                for (int s = 0; s < 2; s++) {
                    const int nt = p * 2 + s;
                    #pragma unroll
                    for (int mt = 0; mt < 2; mt++)
                        mma16816(acc[mt][nt], ah[mt], bh + 2 * s);
                }
            }
        }
        __syncthreads();
    }

    // Epilogue: out = relu(acc + bias), fp32, written once per element.
    // col uses wn*64 ELEMENTS (b_lane's wn*128 is BYTES).
    #pragma unroll
    for (int mt = 0; mt < 2; mt++) {
        int row0 = m0 + wm * 32 + mt * 16 + (lane >> 2);
        #pragma unroll
        for (int nt = 0; nt < 8; nt++) {
            int col = n0 + wn * 64 + nt * 8 + (lane & 3) * 2;
            float b0 = __ldg(bias + col), b1 = __ldg(bias + col + 1);
            float2 v0 = make_float2(fmaxf(acc[mt][nt][0] + b0, 0.f), fmaxf(acc[mt][nt][1] + b1, 0.f));
            float2 v1 = make_float2(fmaxf(acc[mt][nt][2] + b0, 0.f), fmaxf(acc[mt][nt][3] + b1, 0.f));
            *(float2*)(out + (size_t)row0 * OUT_F + col) = v0;
            *(float2*)(out + (size_t)(row0 + 8) * OUT_F + col) = v1;
        }
    }
}

// ---------------------------------------------------------------------------
// Launch: 3 kernels total
// ---------------------------------------------------------------------------
extern "C" void kernel_launch(void* const* d_in, const int* in_sizes, int n_in,
                              void* d_out, int out_size)
{
    const float* text  = (const float*)d_in[0];   // [64,512,256]
    const int*   src   = (const int*)  d_in[1];   // [E]
    const int*   dst   = (const int*)  d_in[2];   // [E]
    const int*   rel   = (const int*)  d_in[3];   // [E]
    const float* bases = (const float*)d_in[4];   // [3,256,256]
    const float* comp  = (const float*)d_in[5];   // [40,3]
    const float* bias  = (const float*)d_in[6];   // [256]
    float* out = (float*)d_out;                   // [64,512,256]

    cudaFuncSetAttribute(gemm_tc_kernel, cudaFuncAttributeMaxDynamicSharedMemorySize, GEMM_SMEM);

    // 1. fp16 converts + bucket scatter (overlapped in one launch;
    //    g_cnt==0 invariant maintained by edge_agg)
    prep_kernel<<<PREP_BLOCKS, 256>>>(text, bases, src, dst, rel);

    // 2. aggregate in input space: z[d,b,:] = sum comp[rel,b]*h[src]
    edge_agg_kernel<<<N_NODES / 8, 256>>>(comp);

    // 3. out = relu(z @ B_stacked + bias) on the tensor pipe
    gemm_tc_kernel<<<dim3(OUT_F / 128, N_NODES / 128), 256, GEMM_SMEM>>>(bias, out);
}